// round 8
// baseline (speedup 1.0000x reference)
#include <cuda_runtime.h>
#include <cuda_bf16.h>
#include <math.h>
#include <cstdint>

#define NN 100000
#define EE 1000000

// ---------------- device scratch (zero-initialized at load; k_clean restores) ----------------
__device__ int    d_cnt[NN];
__device__ int    d_off[NN + 1];
__device__ int    d_cur[NN];
__device__ int    d_scan_tix;
__device__ unsigned long long d_scan_state[128];
__device__ int4   d_adj[EE];                    // {ssrc, eid, pid, 0}
__device__ __nv_bfloat16 d_hagg0[(size_t)NN * 64];
__device__ __nv_bfloat16 d_efp [(size_t)NN * 64];
__device__ __nv_bfloat16 d_efn [(size_t)NN * 64];
__device__ __nv_bfloat16 d_h1p [(size_t)NN * 64];
__device__ __nv_bfloat16 d_h1n [(size_t)NN * 64];
__device__ __nv_bfloat16 d_hp  [(size_t)NN * 64];
__device__ __nv_bfloat16 d_hn  [(size_t)NN * 64];
// folded W in tf32, stored in exact mma B-fragment order
__device__ float  d_Wf[2][3 * 8 * 8 * 64];
__device__ float  d_cv[2][64];
__device__ double d_loss;

// ---------------- helpers ----------------
__device__ __forceinline__ float tf32r(float x) {
    uint32_t r; asm("cvt.rna.tf32.f32 %0, %1;" : "=r"(r) : "f"(x));
    return __uint_as_float(r);
}
__device__ __forceinline__ void mma_tf32(float* c, uint32_t a0, uint32_t a1, uint32_t a2, uint32_t a3,
                                         uint32_t b0, uint32_t b1) {
    asm volatile("mma.sync.aligned.m16n8k8.row.col.f32.tf32.tf32.f32 "
                 "{%0,%1,%2,%3}, {%4,%5,%6,%7}, {%8,%9}, {%0,%1,%2,%3};"
                 : "+f"(c[0]), "+f"(c[1]), "+f"(c[2]), "+f"(c[3])
                 : "r"(a0), "r"(a1), "r"(a2), "r"(a3), "r"(b0), "r"(b1));
}
__device__ __forceinline__ uint32_t bf2(float x, float y) {
    uint32_t r; asm("cvt.rn.satfinite.bf16x2.f32 %0, %1, %2;" : "=r"(r) : "f"(y), "f"(x)); return r;
}
__device__ __forceinline__ float2 bf2f(uint32_t v) {
    __nv_bfloat162 h = *reinterpret_cast<__nv_bfloat162*>(&v);
    return __bfloat1622float2(h);
}
__device__ __forceinline__ void acc4(float4& a, float4 v) {
    a.x += v.x; a.y += v.y; a.z += v.z; a.w += v.w;
}
// reduce across the 4 edge-groups of a warp (lanes differing in bits 3,4)
__device__ __forceinline__ void red4(float4& v) {
    v.x += __shfl_xor_sync(~0u, v.x, 8);  v.y += __shfl_xor_sync(~0u, v.y, 8);
    v.z += __shfl_xor_sync(~0u, v.z, 8);  v.w += __shfl_xor_sync(~0u, v.w, 8);
    v.x += __shfl_xor_sync(~0u, v.x, 16); v.y += __shfl_xor_sync(~0u, v.y, 16);
    v.z += __shfl_xor_sync(~0u, v.z, 16); v.w += __shfl_xor_sync(~0u, v.w, 16);
}

// ---------------- CSR build ----------------
__global__ void k_hist(const int* __restrict__ dst, int E) {
    int e = blockIdx.x * blockDim.x + threadIdx.x;
    if (e < E) atomicAdd(&d_cnt[dst[e]], 1);
}

__global__ void k_scan(int n, int E, int nb) {
    __shared__ int ws[32];
    __shared__ int s_bid;
    __shared__ int s_pref;
    if (threadIdx.x == 0) s_bid = atomicAdd(&d_scan_tix, 1);
    __syncthreads();
    int bid = s_bid;
    int i = bid * 1024 + threadIdx.x;
    int lane = threadIdx.x & 31, wid = threadIdx.x >> 5;
    int v = (i < n) ? d_cnt[i] : 0;
    int x = v;
    #pragma unroll
    for (int o = 1; o < 32; o <<= 1) { int y = __shfl_up_sync(~0u, x, o); if (lane >= o) x += y; }
    if (lane == 31) ws[wid] = x;
    __syncthreads();
    if (wid == 0) {
        int w = ws[lane];
        #pragma unroll
        for (int o = 1; o < 32; o <<= 1) { int y = __shfl_up_sync(~0u, w, o); if (lane >= o) w += y; }
        ws[lane] = w;
    }
    __syncthreads();
    int incl = x + (wid > 0 ? ws[wid - 1] : 0);
    int total = ws[31];
    if (threadIdx.x == 0) {
        if (bid == 0) {
            atomicExch(&d_scan_state[0], (2ULL << 32) | (unsigned)total);
            s_pref = 0;
        } else {
            atomicExch(&d_scan_state[bid], (1ULL << 32) | (unsigned)total);
            int pref = 0;
            for (int j = bid - 1; j >= 0; --j) {
                unsigned long long st;
                do { st = atomicAdd(&d_scan_state[j], 0ULL); } while (!(st >> 32));
                pref += (int)(unsigned)st;
                if ((st >> 32) == 2ULL) break;
            }
            atomicExch(&d_scan_state[bid], (2ULL << 32) | (unsigned)(pref + total));
            s_pref = pref;
        }
    }
    __syncthreads();
    int pref = s_pref;
    if (i < n) d_off[i] = pref + incl - v;
    if (bid == nb - 1 && threadIdx.x == 0) d_off[n] = E;
}

__global__ void k_scatter(const int* __restrict__ src, const int* __restrict__ dst,
                          const int* __restrict__ perm, int E) {
    int e = blockIdx.x * blockDim.x + threadIdx.x;
    if (e < E) {
        int d = dst[e];
        int p = d_off[d] + atomicAdd(&d_cur[d], 1);
        d_adj[p] = make_int4(src[e], e, perm[e], 0);
    }
}

// ---------------- fused first-stage aggregation (fp32 in, bf16 out) ----------------
// 8 lanes per edge, 4 edges in flight per warp; each thread covers 2 float4 per row.
__global__ void k_agg3(const float* __restrict__ nf, const float* __restrict__ ef, int n) {
    int gw = (blockIdx.x * blockDim.x + threadIdx.x) >> 5;
    int lane = threadIdx.x & 31;
    if (gw >= n) return;
    int beg = d_off[gw], end = d_off[gw + 1];
    int g = lane >> 3, q = lane & 7;
    float4 z = make_float4(0.f, 0.f, 0.f, 0.f);
    float4 ah0 = z, ah1 = z, ap0 = z, ap1 = z, an0 = z, an1 = z;
    for (int k = beg + g; k < end; k += 4) {
        int4 a = __ldg(&d_adj[k]);
        const float4* r1 = (const float4*)nf + (size_t)a.x * 16;
        const float4* r2 = (const float4*)ef + (size_t)a.y * 16;
        const float4* r3 = (const float4*)ef + (size_t)a.z * 16;
        float4 x0 = __ldg(r1 + q), x1 = __ldg(r1 + q + 8);
        float4 y0 = __ldg(r2 + q), y1 = __ldg(r2 + q + 8);
        float4 w0 = __ldg(r3 + q), w1 = __ldg(r3 + q + 8);
        acc4(ah0, x0); acc4(ah1, x1);
        acc4(ap0, y0); acc4(ap1, y1);
        acc4(an0, w0); acc4(an1, w1);
    }
    red4(ah0); red4(ah1); red4(ap0); red4(ap1); red4(an0); red4(an1);
    if (lane < 8) {
        float inv = 1.f / fmaxf((float)(end - beg), 1.f);
        uint2* oh = reinterpret_cast<uint2*>(d_hagg0) + (size_t)gw * 16;
        uint2* op = reinterpret_cast<uint2*>(d_efp)   + (size_t)gw * 16;
        uint2* on = reinterpret_cast<uint2*>(d_efn)   + (size_t)gw * 16;
        oh[q]     = make_uint2(bf2(ah0.x * inv, ah0.y * inv), bf2(ah0.z * inv, ah0.w * inv));
        oh[q + 8] = make_uint2(bf2(ah1.x * inv, ah1.y * inv), bf2(ah1.z * inv, ah1.w * inv));
        op[q]     = make_uint2(bf2(ap0.x * inv, ap0.y * inv), bf2(ap0.z * inv, ap0.w * inv));
        op[q + 8] = make_uint2(bf2(ap1.x * inv, ap1.y * inv), bf2(ap1.z * inv, ap1.w * inv));
        on[q]     = make_uint2(bf2(an0.x * inv, an0.y * inv), bf2(an0.z * inv, an0.w * inv));
        on[q + 8] = make_uint2(bf2(an1.x * inv, an1.y * inv), bf2(an1.z * inv, an1.w * inv));
    }
}

// ---------------- second-stage aggregation: hp + hn (bf16 in/out) ----------------
__global__ void k_aggh2(int n) {
    int gw = (blockIdx.x * blockDim.x + threadIdx.x) >> 5;
    int lane = threadIdx.x & 31;
    if (gw >= n) return;
    int beg = d_off[gw], end = d_off[gw + 1];
    int g = lane >> 3, q = lane & 7;
    float4 z = make_float4(0.f, 0.f, 0.f, 0.f);
    float4 aa0 = z, aa1 = z, ab0 = z, ab1 = z;
    const uint2* fa = reinterpret_cast<const uint2*>(d_h1p);
    const uint2* fb = reinterpret_cast<const uint2*>(d_h1n);
    for (int k = beg + g; k < end; k += 4) {
        int s = __ldg(&d_adj[k]).x;
        uint2 v0 = __ldg(fa + (size_t)s * 16 + q);
        uint2 v1 = __ldg(fa + (size_t)s * 16 + q + 8);
        uint2 u0 = __ldg(fb + (size_t)s * 16 + q);
        uint2 u1 = __ldg(fb + (size_t)s * 16 + q + 8);
        float2 t;
        t = bf2f(v0.x); aa0.x += t.x; aa0.y += t.y;  t = bf2f(v0.y); aa0.z += t.x; aa0.w += t.y;
        t = bf2f(v1.x); aa1.x += t.x; aa1.y += t.y;  t = bf2f(v1.y); aa1.z += t.x; aa1.w += t.y;
        t = bf2f(u0.x); ab0.x += t.x; ab0.y += t.y;  t = bf2f(u0.y); ab0.z += t.x; ab0.w += t.y;
        t = bf2f(u1.x); ab1.x += t.x; ab1.y += t.y;  t = bf2f(u1.y); ab1.z += t.x; ab1.w += t.y;
    }
    red4(aa0); red4(aa1); red4(ab0); red4(ab1);
    if (lane < 8) {
        float inv = 1.f / fmaxf((float)(end - beg), 1.f);
        uint2* oa = reinterpret_cast<uint2*>(d_hp) + (size_t)gw * 16;
        uint2* ob = reinterpret_cast<uint2*>(d_hn) + (size_t)gw * 16;
        oa[q]     = make_uint2(bf2(aa0.x * inv, aa0.y * inv), bf2(aa0.z * inv, aa0.w * inv));
        oa[q + 8] = make_uint2(bf2(aa1.x * inv, aa1.y * inv), bf2(aa1.z * inv, aa1.w * inv));
        ob[q]     = make_uint2(bf2(ab0.x * inv, ab0.y * inv), bf2(ab0.z * inv, ab0.w * inv));
        ob[q + 8] = make_uint2(bf2(ab1.x * inv, ab1.y * inv), bf2(ab1.z * inv, ab1.w * inv));
    }
}

// ---------------- fold Wmsg into Wapply -> tf32 B-fragment layout ----------------
__global__ void k_fold2(const float* __restrict__ Wm0, const float* __restrict__ bm0,
                        const float* __restrict__ Wa0,
                        const float* __restrict__ Wm1, const float* __restrict__ bm1,
                        const float* __restrict__ Wa1) {
    int layer = blockIdx.x;
    const float* Wmsg = layer ? Wm1 : Wm0;
    const float* bmsg = layer ? bm1 : bm0;
    const float* Wap  = layer ? Wa1 : Wa0;
    __shared__ float Wn[64][64];
    __shared__ float bm[64];
    int tid = threadIdx.x;
    for (int idx = tid; idx < 64 * 64; idx += 256) {
        int j = idx >> 6, t = idx & 63;
        Wn[t][j] = Wap[j * 128 + 64 + t];
    }
    if (tid < 64) bm[tid] = bmsg[tid];
    __syncthreads();
    for (int idx = tid; idx < 192 * 64; idx += 256) {
        int k = idx >> 6, j = idx & 63;
        float r;
        if (k < 64) {
            r = Wap[j * 128 + k];
        } else {
            int col = k - 64;
            float a = 0.f;
            #pragma unroll
            for (int t = 0; t < 64; ++t) a += Wmsg[t * 128 + col] * Wn[t][j];
            r = a;
        }
        int panel = k >> 6, kk = k & 63;
        int s = kk >> 3, krem = kk & 7;
        int slot = krem >> 2, kq = krem & 3;
        int t = ((j & 7) << 2) | kq;
        int nb = j >> 3;
        int o = ((panel * 8 + s) * 8 + nb) * 64 + t * 2 + slot;
        d_Wf[layer][o] = tf32r(r);
    }
    for (int j = tid; j < 64; j += 256) {
        float a = 0.f;
        #pragma unroll
        for (int t = 0; t < 64; ++t) a += bm[t] * Wn[t][j];
        d_cv[layer][j] = a;
    }
}

// ---------------- mma GEMM building blocks ----------------
#define XST 68
#define SM_X 0
#define SM_W (128 * XST)
#define SM_B (SM_W + 64 * 64)
#define SM_C (SM_B + 64)
#define SM_TOTF (SM_C + 64)
#define GEMM_SMEM (SM_TOTF * 4)

__device__ __forceinline__ void stage_f32(float* __restrict__ Xs, const float* __restrict__ S,
                                          int node0, int n, int tid) {
    #pragma unroll
    for (int it = 0; it < 8; ++it) {
        int t = tid + it * 256;
        int r = t >> 4, c4 = (t & 15) << 2;
        int nd = node0 + r;
        float4 v = make_float4(0.f, 0.f, 0.f, 0.f);
        if (nd < n) v = __ldg(reinterpret_cast<const float4*>(S) + (size_t)nd * 16 + (t & 15));
        v.x = tf32r(v.x); v.y = tf32r(v.y); v.z = tf32r(v.z); v.w = tf32r(v.w);
        *reinterpret_cast<float4*>(Xs + r * XST + c4) = v;
    }
}
__device__ __forceinline__ void stage_bf16(float* __restrict__ Xs, const __nv_bfloat16* __restrict__ S,
                                           int node0, int n, int tid) {
    #pragma unroll
    for (int it = 0; it < 4; ++it) {
        int t = tid + it * 256;
        int r = t >> 3, u4 = t & 7;
        int nd = node0 + r;
        uint4 v = make_uint4(0u, 0u, 0u, 0u);
        if (nd < n) v = __ldg(reinterpret_cast<const uint4*>(S) + (size_t)nd * 8 + u4);
        float2 f0 = bf2f(v.x), f1 = bf2f(v.y), f2 = bf2f(v.z), f3 = bf2f(v.w);
        *reinterpret_cast<float4*>(Xs + r * XST + u4 * 8)     = make_float4(f0.x, f0.y, f1.x, f1.y);
        *reinterpret_cast<float4*>(Xs + r * XST + u4 * 8 + 4) = make_float4(f2.x, f2.y, f3.x, f3.y);
    }
}
__device__ __forceinline__ void stage_w(float* __restrict__ Wp, const float* __restrict__ Wg, int tid) {
    #pragma unroll
    for (int it = 0; it < 4; ++it) {
        int t = tid + it * 256;
        reinterpret_cast<float4*>(Wp)[t] = __ldg(reinterpret_cast<const float4*>(Wg) + t);
    }
}
__device__ __forceinline__ void mma_phase(const float* __restrict__ Xs, const float* __restrict__ Wp,
                                          float* acc, int r0w, int lane) {
    int ar = r0w + (lane >> 2);
    #pragma unroll
    for (int s = 0; s < 8; ++s) {
        int ac = s * 8 + (lane & 3);
        uint32_t a0 = __float_as_uint(Xs[ar * XST + ac]);
        uint32_t a1 = __float_as_uint(Xs[(ar + 8) * XST + ac]);
        uint32_t a2 = __float_as_uint(Xs[ar * XST + ac + 4]);
        uint32_t a3 = __float_as_uint(Xs[(ar + 8) * XST + ac + 4]);
        #pragma unroll
        for (int nb = 0; nb < 8; ++nb) {
            float2 b = *reinterpret_cast<const float2*>(Wp + (s * 8 + nb) * 64 + lane * 2);
            mma_tf32(acc + nb * 4, a0, a1, a2, a3, __float_as_uint(b.x), __float_as_uint(b.y));
        }
    }
}

__device__ __forceinline__ float indf(int nd, int n) {
    return (nd < n && d_off[nd + 1] > d_off[nd]) ? 1.f : 0.f;
}

__device__ __forceinline__ void epi0(const float* acc, const float* __restrict__ sb,
                                     const float* __restrict__ sc, __nv_bfloat16* __restrict__ out,
                                     int node0, int r0w, int lane, int n) {
    int rA = node0 + r0w + (lane >> 2);
    int rB = rA + 8;
    float indA = indf(rA, n), indB = indf(rB, n);
    uint32_t* o32 = reinterpret_cast<uint32_t*>(out);
    #pragma unroll
    for (int nb = 0; nb < 8; ++nb) {
        int cc = nb * 8 + (lane & 3) * 2;
        float xA0 = fmaxf(acc[nb*4+0] + sb[cc]   + indA * sc[cc],   0.f);
        float xA1 = fmaxf(acc[nb*4+1] + sb[cc+1] + indA * sc[cc+1], 0.f);
        float xB0 = fmaxf(acc[nb*4+2] + sb[cc]   + indB * sc[cc],   0.f);
        float xB1 = fmaxf(acc[nb*4+3] + sb[cc+1] + indB * sc[cc+1], 0.f);
        if (rA < n) o32[(size_t)rA * 32 + (cc >> 1)] = bf2(xA0, xA1);
        if (rB < n) o32[(size_t)rB * 32 + (cc >> 1)] = bf2(xB0, xB1);
    }
}

// ---------------- layer 0 ----------------
__global__ void __launch_bounds__(256) k_l0(
    const float* __restrict__ nfeats, const float* __restrict__ bap, int n)
{
    extern __shared__ float sm[];
    float* Xs = sm + SM_X;
    float* Wp = sm + SM_W;
    float* sb = sm + SM_B;
    float* sc = sm + SM_C;
    int tid = threadIdx.x, wid = tid >> 5, lane = tid & 31;
    int node0 = blockIdx.x * 128;
    int r0w = wid * 16;
    if (tid < 64) { sb[tid] = bap[tid]; sc[tid] = d_cv[0][tid]; }

    float acc[32], accB[32];
    #pragma unroll
    for (int i = 0; i < 32; ++i) acc[i] = 0.f;

    stage_f32(Xs, nfeats, node0, n, tid);
    stage_w(Wp, d_Wf[0], tid);
    __syncthreads();
    mma_phase(Xs, Wp, acc, r0w, lane);
    __syncthreads();

    stage_bf16(Xs, d_hagg0, node0, n, tid);
    stage_w(Wp, d_Wf[0] + 4096, tid);
    __syncthreads();
    mma_phase(Xs, Wp, acc, r0w, lane);
    __syncthreads();
    #pragma unroll
    for (int i = 0; i < 32; ++i) accB[i] = acc[i];

    stage_bf16(Xs, d_efp, node0, n, tid);
    stage_w(Wp, d_Wf[0] + 8192, tid);
    __syncthreads();
    mma_phase(Xs, Wp, acc, r0w, lane);
    epi0(acc, sb, sc, d_h1p, node0, r0w, lane, n);
    __syncthreads();

    stage_bf16(Xs, d_efn, node0, n, tid);
    __syncthreads();
    #pragma unroll
    for (int i = 0; i < 32; ++i) acc[i] = accB[i];
    mma_phase(Xs, Wp, acc, r0w, lane);
    epi0(acc, sb, sc, d_h1n, node0, r0w, lane, n);
}

// ---------------- layer 1 ----------------
__global__ void __launch_bounds__(256) k_l1(const float* __restrict__ bap, int n)
{
    extern __shared__ float sm[];
    float* Xs = sm + SM_X;
    float* Wp = sm + SM_W;
    float* sb = sm + SM_B;
    float* sc = sm + SM_C;
    __shared__ float wred[8];
    int tid = threadIdx.x, wid = tid >> 5, lane = tid & 31;
    int node0 = blockIdx.x * 128;
    int r0w = wid * 16;
    int view = blockIdx.y;
    if (tid < 64) { sb[tid] = bap[tid]; sc[tid] = d_cv[1][tid]; }

    const __nv_bfloat16* S0 = view ? d_h1n : d_h1p;
    const __nv_bfloat16* S1 = view ? d_hn  : d_hp;
    const __nv_bfloat16* S2 = view ? d_efn : d_efp;

    float acc[32];
    #pragma unroll
    for (int i = 0; i < 32; ++i) acc[i] = 0.f;

    #pragma unroll
    for (int p = 0; p < 3; ++p) {
        const __nv_bfloat16* S = (p == 0) ? S0 : (p == 1) ? S1 : S2;
        if (p) __syncthreads();
        stage_bf16(Xs, S, node0, n, tid);
        stage_w(Wp, d_Wf[1] + p * 4096, tid);
        __syncthreads();
        mma_phase(Xs, Wp, acc, r0w, lane);
    }

    int rA = node0 + r0w + (lane >> 2);
    int rB = rA + 8;
    float indA = indf(rA, n), indB = indf(rB, n);
    float lsum = 0.f;
    #pragma unroll
    for (int nb = 0; nb < 8; ++nb) {
        int cc = nb * 8 + (lane & 3) * 2;
        float xA0 = fmaxf(acc[nb*4+0] + sb[cc]   + indA * sc[cc],   0.f);
        float xA1 = fmaxf(acc[nb*4+1] + sb[cc+1] + indA * sc[cc+1], 0.f);
        float xB0 = fmaxf(acc[nb*4+2] + sb[cc]   + indB * sc[cc],   0.f);
        float xB1 = fmaxf(acc[nb*4+3] + sb[cc+1] + indB * sc[cc+1], 0.f);
        if (rA < n) {
            float t0 = log1pf(expf(-xA0)), t1 = log1pf(expf(-xA1));
            lsum += view ? (xA0 + t0 + xA1 + t1) : (t0 + t1);
        }
        if (rB < n) {
            float t0 = log1pf(expf(-xB0)), t1 = log1pf(expf(-xB1));
            lsum += view ? (xB0 + t0 + xB1 + t1) : (t0 + t1);
        }
    }
    #pragma unroll
    for (int o = 16; o; o >>= 1) lsum += __shfl_down_sync(~0u, lsum, o);
    if (lane == 0) wred[wid] = lsum;
    __syncthreads();
    if (tid < 8) {
        float s = wred[tid];
        #pragma unroll
        for (int o = 4; o; o >>= 1) s += __shfl_down_sync(0xffu, s, o);
        if (tid == 0) atomicAdd(&d_loss, (double)s);
    }
}

// ---------------- write result + restore zero-state invariant ----------------
__global__ void k_clean(float* out, double denom, int n) {
    int i = blockIdx.x * blockDim.x + threadIdx.x;
    if (i == 0) {
        out[0] = (float)(d_loss / denom);
        d_loss = 0.0;
        d_scan_tix = 0;
    }
    if (i < 128) d_scan_state[i] = 0ULL;
    if (i < n) { d_cnt[i] = 0; d_cur[i] = 0; }
}

// ---------------- launch ----------------
extern "C" void kernel_launch(void* const* d_in, const int* in_sizes, int n_in,
                              void* d_out, int out_size) {
    const float* nfeats = (const float*)d_in[0];
    const float* efeats = (const float*)d_in[1];
    const int*   src    = (const int*)d_in[2];
    const int*   dst    = (const int*)d_in[3];
    const int*   perm   = (const int*)d_in[4];
    const float* Wm0 = (const float*)d_in[5];
    const float* bm0 = (const float*)d_in[6];
    const float* Wa0 = (const float*)d_in[7];
    const float* ba0 = (const float*)d_in[8];
    const float* Wm1 = (const float*)d_in[9];
    const float* bm1 = (const float*)d_in[10];
    const float* Wa1 = (const float*)d_in[11];
    const float* ba1 = (const float*)d_in[12];

    int n = in_sizes[0] / 64;
    int E = in_sizes[2];
    int nb = (n + 1023) / 1024;

    cudaFuncSetAttribute(k_l0, cudaFuncAttributeMaxDynamicSharedMemorySize, GEMM_SMEM);
    cudaFuncSetAttribute(k_l1, cudaFuncAttributeMaxDynamicSharedMemorySize, GEMM_SMEM);

    int gw = (n * 32 + 255) / 256;  // one warp per node
    int gl = (n + 127) / 128;       // 128 nodes per tile

    k_hist   <<<(E + 255) / 256, 256>>>(dst, E);             // 1
    k_scan   <<<nb, 1024>>>(n, E, nb);                       // 2
    k_scatter<<<(E + 255) / 256, 256>>>(src, dst, perm, E);  // 3
    k_agg3   <<<gw, 256>>>(nfeats, efeats, n);               // 4 <- profiled
    k_fold2  <<<2, 256>>>(Wm0, bm0, Wa0, Wm1, bm1, Wa1);     // 5
    k_l0     <<<gl, 256, GEMM_SMEM>>>(nfeats, ba0, n);       // 6
    k_aggh2  <<<gw, 256>>>(n);                               // 7
    {
        dim3 grid(gl, 2);
        k_l1 <<<grid, 256, GEMM_SMEM>>>(ba1, n);             // 8
    }
    k_clean  <<<(n + 255) / 256, 256>>>((float*)d_out, (double)n * 64.0, n); // 9
}

// round 9
// speedup vs baseline: 1.1273x; 1.1273x over previous
#include <cuda_runtime.h>
#include <cuda_bf16.h>
#include <math.h>
#include <cstdint>

#define NN 100000
#define EE 1000000

// ---------------- device scratch (zero-initialized at load; k_clean restores) ----------------
__device__ int    d_cnt[NN];
__device__ int    d_off[NN + 1];
__device__ int    d_cur[NN];
__device__ int    d_scan_tix;
__device__ unsigned long long d_scan_state[128];
__device__ int4   d_adj[EE];                    // {ssrc, eid, pid, 0}
__device__ __nv_bfloat16 d_hagg0[(size_t)NN * 64];
__device__ __nv_bfloat16 d_efp [(size_t)NN * 64];
__device__ __nv_bfloat16 d_efn [(size_t)NN * 64];
__device__ __nv_bfloat16 d_h1p [(size_t)NN * 64];
__device__ __nv_bfloat16 d_h1n [(size_t)NN * 64];
__device__ __nv_bfloat16 d_hp  [(size_t)NN * 64];
__device__ __nv_bfloat16 d_hn  [(size_t)NN * 64];
// folded W in tf32, stored in exact mma B-fragment order
__device__ float  d_Wf[2][3 * 8 * 8 * 64];
__device__ float  d_cv[2][64];
__device__ double d_loss;

// ---------------- helpers ----------------
__device__ __forceinline__ float tf32r(float x) {
    uint32_t r; asm("cvt.rna.tf32.f32 %0, %1;" : "=r"(r) : "f"(x));
    return __uint_as_float(r);
}
__device__ __forceinline__ void mma_tf32(float* c, uint32_t a0, uint32_t a1, uint32_t a2, uint32_t a3,
                                         uint32_t b0, uint32_t b1) {
    asm volatile("mma.sync.aligned.m16n8k8.row.col.f32.tf32.tf32.f32 "
                 "{%0,%1,%2,%3}, {%4,%5,%6,%7}, {%8,%9}, {%0,%1,%2,%3};"
                 : "+f"(c[0]), "+f"(c[1]), "+f"(c[2]), "+f"(c[3])
                 : "r"(a0), "r"(a1), "r"(a2), "r"(a3), "r"(b0), "r"(b1));
}
__device__ __forceinline__ uint32_t bf2(float x, float y) {
    uint32_t r; asm("cvt.rn.satfinite.bf16x2.f32 %0, %1, %2;" : "=r"(r) : "f"(y), "f"(x)); return r;
}
__device__ __forceinline__ float2 bf2f(uint32_t v) {
    __nv_bfloat162 h = *reinterpret_cast<__nv_bfloat162*>(&v);
    return __bfloat1622float2(h);
}

// ---------------- CSR build ----------------
__global__ void k_hist(const int* __restrict__ dst, int E) {
    int e = blockIdx.x * blockDim.x + threadIdx.x;
    if (e < E) atomicAdd(&d_cnt[dst[e]], 1);
}

__global__ void k_scan(int n, int E, int nb) {
    __shared__ int ws[32];
    __shared__ int s_bid;
    __shared__ int s_pref;
    if (threadIdx.x == 0) s_bid = atomicAdd(&d_scan_tix, 1);
    __syncthreads();
    int bid = s_bid;
    int i = bid * 1024 + threadIdx.x;
    int lane = threadIdx.x & 31, wid = threadIdx.x >> 5;
    int v = (i < n) ? d_cnt[i] : 0;
    int x = v;
    #pragma unroll
    for (int o = 1; o < 32; o <<= 1) { int y = __shfl_up_sync(~0u, x, o); if (lane >= o) x += y; }
    if (lane == 31) ws[wid] = x;
    __syncthreads();
    if (wid == 0) {
        int w = ws[lane];
        #pragma unroll
        for (int o = 1; o < 32; o <<= 1) { int y = __shfl_up_sync(~0u, w, o); if (lane >= o) w += y; }
        ws[lane] = w;
    }
    __syncthreads();
    int incl = x + (wid > 0 ? ws[wid - 1] : 0);
    int total = ws[31];
    if (threadIdx.x == 0) {
        if (bid == 0) {
            atomicExch(&d_scan_state[0], (2ULL << 32) | (unsigned)total);
            s_pref = 0;
        } else {
            atomicExch(&d_scan_state[bid], (1ULL << 32) | (unsigned)total);
            int pref = 0;
            for (int j = bid - 1; j >= 0; --j) {
                unsigned long long st;
                do { st = atomicAdd(&d_scan_state[j], 0ULL); } while (!(st >> 32));
                pref += (int)(unsigned)st;
                if ((st >> 32) == 2ULL) break;
            }
            atomicExch(&d_scan_state[bid], (2ULL << 32) | (unsigned)(pref + total));
            s_pref = pref;
        }
    }
    __syncthreads();
    int pref = s_pref;
    if (i < n) d_off[i] = pref + incl - v;
    if (bid == nb - 1 && threadIdx.x == 0) d_off[n] = E;
}

__global__ void k_scatter(const int* __restrict__ src, const int* __restrict__ dst,
                          const int* __restrict__ perm, int E) {
    int e = blockIdx.x * blockDim.x + threadIdx.x;
    if (e < E) {
        int d = dst[e];
        int p = d_off[d] + atomicAdd(&d_cur[d], 1);
        d_adj[p] = make_int4(src[e], e, perm[e], 0);
    }
}

// ---------------- fused first-stage aggregation ----------------
// Lane-per-column: lane owns float columns [2*lane, 2*lane+1]; no reduction needed.
// Unroll-by-4 with distinct registers -> 12 feature loads in flight per warp.
__global__ void __launch_bounds__(256) k_agg3(const float* __restrict__ nf,
                                              const float* __restrict__ ef, int n) {
    int gw = (blockIdx.x * blockDim.x + threadIdx.x) >> 5;
    int lane = threadIdx.x & 31;
    if (gw >= n) return;
    int beg = d_off[gw], end = d_off[gw + 1];
    const float2* nf2 = (const float2*)nf;
    const float2* ef2 = (const float2*)ef;
    float2 ah = make_float2(0.f, 0.f), ap = ah, an = ah;
    int k = beg;
    for (; k + 4 <= end; k += 4) {
        int4 a0 = __ldg(&d_adj[k]);
        int4 a1 = __ldg(&d_adj[k + 1]);
        int4 a2 = __ldg(&d_adj[k + 2]);
        int4 a3 = __ldg(&d_adj[k + 3]);
        float2 h0 = __ldg(nf2 + (a0.x * 32 + lane));
        float2 p0 = __ldg(ef2 + (a0.y * 32 + lane));
        float2 q0 = __ldg(ef2 + (a0.z * 32 + lane));
        float2 h1 = __ldg(nf2 + (a1.x * 32 + lane));
        float2 p1 = __ldg(ef2 + (a1.y * 32 + lane));
        float2 q1 = __ldg(ef2 + (a1.z * 32 + lane));
        float2 h2 = __ldg(nf2 + (a2.x * 32 + lane));
        float2 p2 = __ldg(ef2 + (a2.y * 32 + lane));
        float2 q2 = __ldg(ef2 + (a2.z * 32 + lane));
        float2 h3 = __ldg(nf2 + (a3.x * 32 + lane));
        float2 p3 = __ldg(ef2 + (a3.y * 32 + lane));
        float2 q3 = __ldg(ef2 + (a3.z * 32 + lane));
        ah.x += (h0.x + h1.x) + (h2.x + h3.x);
        ah.y += (h0.y + h1.y) + (h2.y + h3.y);
        ap.x += (p0.x + p1.x) + (p2.x + p3.x);
        ap.y += (p0.y + p1.y) + (p2.y + p3.y);
        an.x += (q0.x + q1.x) + (q2.x + q3.x);
        an.y += (q0.y + q1.y) + (q2.y + q3.y);
    }
    for (; k < end; ++k) {
        int4 a = __ldg(&d_adj[k]);
        float2 h = __ldg(nf2 + (a.x * 32 + lane));
        float2 p = __ldg(ef2 + (a.y * 32 + lane));
        float2 q = __ldg(ef2 + (a.z * 32 + lane));
        ah.x += h.x; ah.y += h.y;
        ap.x += p.x; ap.y += p.y;
        an.x += q.x; an.y += q.y;
    }
    float inv = 1.f / fmaxf((float)(end - beg), 1.f);
    reinterpret_cast<uint32_t*>(d_hagg0)[(size_t)gw * 32 + lane] = bf2(ah.x * inv, ah.y * inv);
    reinterpret_cast<uint32_t*>(d_efp)  [(size_t)gw * 32 + lane] = bf2(ap.x * inv, ap.y * inv);
    reinterpret_cast<uint32_t*>(d_efn)  [(size_t)gw * 32 + lane] = bf2(an.x * inv, an.y * inv);
}

// ---------------- second-stage aggregation: hp + hn (bf16 in/out) ----------------
// Lane owns bf16x2 column [lane]; unroll-by-4.
__global__ void __launch_bounds__(256) k_aggh2(int n) {
    int gw = (blockIdx.x * blockDim.x + threadIdx.x) >> 5;
    int lane = threadIdx.x & 31;
    if (gw >= n) return;
    int beg = d_off[gw], end = d_off[gw + 1];
    const uint32_t* fa = reinterpret_cast<const uint32_t*>(d_h1p);
    const uint32_t* fb = reinterpret_cast<const uint32_t*>(d_h1n);
    const int* adjs = reinterpret_cast<const int*>(d_adj);
    float2 aa = make_float2(0.f, 0.f), ab = aa;
    int k = beg;
    for (; k + 4 <= end; k += 4) {
        int s0 = __ldg(adjs + 4 * k);
        int s1 = __ldg(adjs + 4 * (k + 1));
        int s2 = __ldg(adjs + 4 * (k + 2));
        int s3 = __ldg(adjs + 4 * (k + 3));
        uint32_t v0 = __ldg(fa + (s0 * 32 + lane));
        uint32_t u0 = __ldg(fb + (s0 * 32 + lane));
        uint32_t v1 = __ldg(fa + (s1 * 32 + lane));
        uint32_t u1 = __ldg(fb + (s1 * 32 + lane));
        uint32_t v2 = __ldg(fa + (s2 * 32 + lane));
        uint32_t u2 = __ldg(fb + (s2 * 32 + lane));
        uint32_t v3 = __ldg(fa + (s3 * 32 + lane));
        uint32_t u3 = __ldg(fb + (s3 * 32 + lane));
        float2 t;
        t = bf2f(v0); aa.x += t.x; aa.y += t.y;
        t = bf2f(v1); aa.x += t.x; aa.y += t.y;
        t = bf2f(v2); aa.x += t.x; aa.y += t.y;
        t = bf2f(v3); aa.x += t.x; aa.y += t.y;
        t = bf2f(u0); ab.x += t.x; ab.y += t.y;
        t = bf2f(u1); ab.x += t.x; ab.y += t.y;
        t = bf2f(u2); ab.x += t.x; ab.y += t.y;
        t = bf2f(u3); ab.x += t.x; ab.y += t.y;
    }
    for (; k < end; ++k) {
        int s = __ldg(adjs + 4 * k);
        uint32_t v = __ldg(fa + (s * 32 + lane));
        uint32_t u = __ldg(fb + (s * 32 + lane));
        float2 t;
        t = bf2f(v); aa.x += t.x; aa.y += t.y;
        t = bf2f(u); ab.x += t.x; ab.y += t.y;
    }
    float inv = 1.f / fmaxf((float)(end - beg), 1.f);
    reinterpret_cast<uint32_t*>(d_hp)[(size_t)gw * 32 + lane] = bf2(aa.x * inv, aa.y * inv);
    reinterpret_cast<uint32_t*>(d_hn)[(size_t)gw * 32 + lane] = bf2(ab.x * inv, ab.y * inv);
}

// ---------------- fold Wmsg into Wapply -> tf32 B-fragment layout ----------------
__global__ void k_fold2(const float* __restrict__ Wm0, const float* __restrict__ bm0,
                        const float* __restrict__ Wa0,
                        const float* __restrict__ Wm1, const float* __restrict__ bm1,
                        const float* __restrict__ Wa1) {
    int layer = blockIdx.x;
    const float* Wmsg = layer ? Wm1 : Wm0;
    const float* bmsg = layer ? bm1 : bm0;
    const float* Wap  = layer ? Wa1 : Wa0;
    __shared__ float Wn[64][64];
    __shared__ float bm[64];
    int tid = threadIdx.x;
    for (int idx = tid; idx < 64 * 64; idx += 256) {
        int j = idx >> 6, t = idx & 63;
        Wn[t][j] = Wap[j * 128 + 64 + t];
    }
    if (tid < 64) bm[tid] = bmsg[tid];
    __syncthreads();
    for (int idx = tid; idx < 192 * 64; idx += 256) {
        int k = idx >> 6, j = idx & 63;
        float r;
        if (k < 64) {
            r = Wap[j * 128 + k];
        } else {
            int col = k - 64;
            float a = 0.f;
            #pragma unroll
            for (int t = 0; t < 64; ++t) a += Wmsg[t * 128 + col] * Wn[t][j];
            r = a;
        }
        int panel = k >> 6, kk = k & 63;
        int s = kk >> 3, krem = kk & 7;
        int slot = krem >> 2, kq = krem & 3;
        int t = ((j & 7) << 2) | kq;
        int nb = j >> 3;
        int o = ((panel * 8 + s) * 8 + nb) * 64 + t * 2 + slot;
        d_Wf[layer][o] = tf32r(r);
    }
    for (int j = tid; j < 64; j += 256) {
        float a = 0.f;
        #pragma unroll
        for (int t = 0; t < 64; ++t) a += bm[t] * Wn[t][j];
        d_cv[layer][j] = a;
    }
}

// ---------------- mma GEMM building blocks ----------------
#define XST 68
#define SM_X 0
#define SM_W (128 * XST)
#define SM_B (SM_W + 64 * 64)
#define SM_C (SM_B + 64)
#define SM_TOTF (SM_C + 64)
#define GEMM_SMEM (SM_TOTF * 4)

__device__ __forceinline__ void stage_f32(float* __restrict__ Xs, const float* __restrict__ S,
                                          int node0, int n, int tid) {
    #pragma unroll
    for (int it = 0; it < 8; ++it) {
        int t = tid + it * 256;
        int r = t >> 4, c4 = (t & 15) << 2;
        int nd = node0 + r;
        float4 v = make_float4(0.f, 0.f, 0.f, 0.f);
        if (nd < n) v = __ldg(reinterpret_cast<const float4*>(S) + (size_t)nd * 16 + (t & 15));
        v.x = tf32r(v.x); v.y = tf32r(v.y); v.z = tf32r(v.z); v.w = tf32r(v.w);
        *reinterpret_cast<float4*>(Xs + r * XST + c4) = v;
    }
}
__device__ __forceinline__ void stage_bf16(float* __restrict__ Xs, const __nv_bfloat16* __restrict__ S,
                                           int node0, int n, int tid) {
    #pragma unroll
    for (int it = 0; it < 4; ++it) {
        int t = tid + it * 256;
        int r = t >> 3, u4 = t & 7;
        int nd = node0 + r;
        uint4 v = make_uint4(0u, 0u, 0u, 0u);
        if (nd < n) v = __ldg(reinterpret_cast<const uint4*>(S) + (size_t)nd * 8 + u4);
        float2 f0 = bf2f(v.x), f1 = bf2f(v.y), f2 = bf2f(v.z), f3 = bf2f(v.w);
        *reinterpret_cast<float4*>(Xs + r * XST + u4 * 8)     = make_float4(f0.x, f0.y, f1.x, f1.y);
        *reinterpret_cast<float4*>(Xs + r * XST + u4 * 8 + 4) = make_float4(f2.x, f2.y, f3.x, f3.y);
    }
}
__device__ __forceinline__ void stage_w(float* __restrict__ Wp, const float* __restrict__ Wg, int tid) {
    #pragma unroll
    for (int it = 0; it < 4; ++it) {
        int t = tid + it * 256;
        reinterpret_cast<float4*>(Wp)[t] = __ldg(reinterpret_cast<const float4*>(Wg) + t);
    }
}
__device__ __forceinline__ void mma_phase(const float* __restrict__ Xs, const float* __restrict__ Wp,
                                          float* acc, int r0w, int lane) {
    int ar = r0w + (lane >> 2);
    #pragma unroll
    for (int s = 0; s < 8; ++s) {
        int ac = s * 8 + (lane & 3);
        uint32_t a0 = __float_as_uint(Xs[ar * XST + ac]);
        uint32_t a1 = __float_as_uint(Xs[(ar + 8) * XST + ac]);
        uint32_t a2 = __float_as_uint(Xs[ar * XST + ac + 4]);
        uint32_t a3 = __float_as_uint(Xs[(ar + 8) * XST + ac + 4]);
        #pragma unroll
        for (int nb = 0; nb < 8; ++nb) {
            float2 b = *reinterpret_cast<const float2*>(Wp + (s * 8 + nb) * 64 + lane * 2);
            mma_tf32(acc + nb * 4, a0, a1, a2, a3, __float_as_uint(b.x), __float_as_uint(b.y));
        }
    }
}

__device__ __forceinline__ float indf(int nd, int n) {
    return (nd < n && d_off[nd + 1] > d_off[nd]) ? 1.f : 0.f;
}

__device__ __forceinline__ void epi0(const float* acc, const float* __restrict__ sb,
                                     const float* __restrict__ sc, __nv_bfloat16* __restrict__ out,
                                     int node0, int r0w, int lane, int n) {
    int rA = node0 + r0w + (lane >> 2);
    int rB = rA + 8;
    float indA = indf(rA, n), indB = indf(rB, n);
    uint32_t* o32 = reinterpret_cast<uint32_t*>(out);
    #pragma unroll
    for (int nb = 0; nb < 8; ++nb) {
        int cc = nb * 8 + (lane & 3) * 2;
        float xA0 = fmaxf(acc[nb*4+0] + sb[cc]   + indA * sc[cc],   0.f);
        float xA1 = fmaxf(acc[nb*4+1] + sb[cc+1] + indA * sc[cc+1], 0.f);
        float xB0 = fmaxf(acc[nb*4+2] + sb[cc]   + indB * sc[cc],   0.f);
        float xB1 = fmaxf(acc[nb*4+3] + sb[cc+1] + indB * sc[cc+1], 0.f);
        if (rA < n) o32[(size_t)rA * 32 + (cc >> 1)] = bf2(xA0, xA1);
        if (rB < n) o32[(size_t)rB * 32 + (cc >> 1)] = bf2(xB0, xB1);
    }
}

// ---------------- layer 0 ----------------
__global__ void __launch_bounds__(256) k_l0(
    const float* __restrict__ nfeats, const float* __restrict__ bap, int n)
{
    extern __shared__ float sm[];
    float* Xs = sm + SM_X;
    float* Wp = sm + SM_W;
    float* sb = sm + SM_B;
    float* sc = sm + SM_C;
    int tid = threadIdx.x, wid = tid >> 5, lane = tid & 31;
    int node0 = blockIdx.x * 128;
    int r0w = wid * 16;
    if (tid < 64) { sb[tid] = bap[tid]; sc[tid] = d_cv[0][tid]; }

    float acc[32], accB[32];
    #pragma unroll
    for (int i = 0; i < 32; ++i) acc[i] = 0.f;

    stage_f32(Xs, nfeats, node0, n, tid);
    stage_w(Wp, d_Wf[0], tid);
    __syncthreads();
    mma_phase(Xs, Wp, acc, r0w, lane);
    __syncthreads();

    stage_bf16(Xs, d_hagg0, node0, n, tid);
    stage_w(Wp, d_Wf[0] + 4096, tid);
    __syncthreads();
    mma_phase(Xs, Wp, acc, r0w, lane);
    __syncthreads();
    #pragma unroll
    for (int i = 0; i < 32; ++i) accB[i] = acc[i];

    stage_bf16(Xs, d_efp, node0, n, tid);
    stage_w(Wp, d_Wf[0] + 8192, tid);
    __syncthreads();
    mma_phase(Xs, Wp, acc, r0w, lane);
    epi0(acc, sb, sc, d_h1p, node0, r0w, lane, n);
    __syncthreads();

    stage_bf16(Xs, d_efn, node0, n, tid);
    __syncthreads();
    #pragma unroll
    for (int i = 0; i < 32; ++i) acc[i] = accB[i];
    mma_phase(Xs, Wp, acc, r0w, lane);
    epi0(acc, sb, sc, d_h1n, node0, r0w, lane, n);
}

// ---------------- layer 1 ----------------
__global__ void __launch_bounds__(256) k_l1(const float* __restrict__ bap, int n)
{
    extern __shared__ float sm[];
    float* Xs = sm + SM_X;
    float* Wp = sm + SM_W;
    float* sb = sm + SM_B;
    float* sc = sm + SM_C;
    __shared__ float wred[8];
    int tid = threadIdx.x, wid = tid >> 5, lane = tid & 31;
    int node0 = blockIdx.x * 128;
    int r0w = wid * 16;
    int view = blockIdx.y;
    if (tid < 64) { sb[tid] = bap[tid]; sc[tid] = d_cv[1][tid]; }

    const __nv_bfloat16* S0 = view ? d_h1n : d_h1p;
    const __nv_bfloat16* S1 = view ? d_hn  : d_hp;
    const __nv_bfloat16* S2 = view ? d_efn : d_efp;

    float acc[32];
    #pragma unroll
    for (int i = 0; i < 32; ++i) acc[i] = 0.f;

    #pragma unroll
    for (int p = 0; p < 3; ++p) {
        const __nv_bfloat16* S = (p == 0) ? S0 : (p == 1) ? S1 : S2;
        if (p) __syncthreads();
        stage_bf16(Xs, S, node0, n, tid);
        stage_w(Wp, d_Wf[1] + p * 4096, tid);
        __syncthreads();
        mma_phase(Xs, Wp, acc, r0w, lane);
    }

    int rA = node0 + r0w + (lane >> 2);
    int rB = rA + 8;
    float indA = indf(rA, n), indB = indf(rB, n);
    float lsum = 0.f;
    #pragma unroll
    for (int nb = 0; nb < 8; ++nb) {
        int cc = nb * 8 + (lane & 3) * 2;
        float xA0 = fmaxf(acc[nb*4+0] + sb[cc]   + indA * sc[cc],   0.f);
        float xA1 = fmaxf(acc[nb*4+1] + sb[cc+1] + indA * sc[cc+1], 0.f);
        float xB0 = fmaxf(acc[nb*4+2] + sb[cc]   + indB * sc[cc],   0.f);
        float xB1 = fmaxf(acc[nb*4+3] + sb[cc+1] + indB * sc[cc+1], 0.f);
        if (rA < n) {
            float t0 = log1pf(expf(-xA0)), t1 = log1pf(expf(-xA1));
            lsum += view ? (xA0 + t0 + xA1 + t1) : (t0 + t1);
        }
        if (rB < n) {
            float t0 = log1pf(expf(-xB0)), t1 = log1pf(expf(-xB1));
            lsum += view ? (xB0 + t0 + xB1 + t1) : (t0 + t1);
        }
    }
    #pragma unroll
    for (int o = 16; o; o >>= 1) lsum += __shfl_down_sync(~0u, lsum, o);
    if (lane == 0) wred[wid] = lsum;
    __syncthreads();
    if (tid < 8) {
        float s = wred[tid];
        #pragma unroll
        for (int o = 4; o; o >>= 1) s += __shfl_down_sync(0xffu, s, o);
        if (tid == 0) atomicAdd(&d_loss, (double)s);
    }
}

// ---------------- write result + restore zero-state invariant ----------------
__global__ void k_clean(float* out, double denom, int n) {
    int i = blockIdx.x * blockDim.x + threadIdx.x;
    if (i == 0) {
        out[0] = (float)(d_loss / denom);
        d_loss = 0.0;
        d_scan_tix = 0;
    }
    if (i < 128) d_scan_state[i] = 0ULL;
    if (i < n) { d_cnt[i] = 0; d_cur[i] = 0; }
}

// ---------------- launch ----------------
extern "C" void kernel_launch(void* const* d_in, const int* in_sizes, int n_in,
                              void* d_out, int out_size) {
    const float* nfeats = (const float*)d_in[0];
    const float* efeats = (const float*)d_in[1];
    const int*   src    = (const int*)d_in[2];
    const int*   dst    = (const int*)d_in[3];
    const int*   perm   = (const int*)d_in[4];
    const float* Wm0 = (const float*)d_in[5];
    const float* bm0 = (const float*)d_in[6];
    const float* Wa0 = (const float*)d_in[7];
    const float* ba0 = (const float*)d_in[8];
    const float* Wm1 = (const float*)d_in[9];
    const float* bm1 = (const float*)d_in[10];
    const float* Wa1 = (const float*)d_in[11];
    const float* ba1 = (const float*)d_in[12];

    int n = in_sizes[0] / 64;
    int E = in_sizes[2];
    int nb = (n + 1023) / 1024;

    cudaFuncSetAttribute(k_l0, cudaFuncAttributeMaxDynamicSharedMemorySize, GEMM_SMEM);
    cudaFuncSetAttribute(k_l1, cudaFuncAttributeMaxDynamicSharedMemorySize, GEMM_SMEM);

    int gw = (n * 32 + 255) / 256;  // one warp per node
    int gl = (n + 127) / 128;       // 128 nodes per tile

    k_hist   <<<(E + 255) / 256, 256>>>(dst, E);             // 1
    k_scan   <<<nb, 1024>>>(n, E, nb);                       // 2
    k_scatter<<<(E + 255) / 256, 256>>>(src, dst, perm, E);  // 3
    k_agg3   <<<gw, 256>>>(nfeats, efeats, n);               // 4 <- profiled
    k_fold2  <<<2, 256>>>(Wm0, bm0, Wa0, Wm1, bm1, Wa1);     // 5
    k_l0     <<<gl, 256, GEMM_SMEM>>>(nfeats, ba0, n);       // 6
    k_aggh2  <<<gw, 256>>>(n);                               // 7
    {
        dim3 grid(gl, 2);
        k_l1 <<<grid, 256, GEMM_SMEM>>>(ba1, n);             // 8
    }
    k_clean  <<<(n + 255) / 256, 256>>>((float*)d_out, (double)n * 64.0, n); // 9
}